// round 3
// baseline (speedup 1.0000x reference)
#include <cuda_runtime.h>
#include <stdint.h>

#define BATCH  2
#define SEQ    2048
#define DMODEL 1024
#define NHEAD  16
#define HDIM   64
#define D3     3072

// Scratch. K stored TRANSPOSED: [B,H,HDIM,SEQ].
__device__ __align__(16) float g_Q   [BATCH * NHEAD * SEQ * HDIM];
__device__ __align__(16) float g_Kt  [BATCH * NHEAD * HDIM * SEQ];
__device__ __align__(16) float g_V   [BATCH * NHEAD * SEQ * HDIM];
__device__ __align__(16) float g_vals[BATCH * SEQ * DMODEL];

// ---- tf32 helpers ----------------------------------------------------------
__device__ __forceinline__ uint32_t f2tf(float x) {
    uint32_t u; asm("cvt.rna.tf32.f32 %0, %1;" : "=r"(u) : "f"(x)); return u;
}
__device__ __forceinline__ uint2 split2(float x) {
    uint2 r; r.x = f2tf(x); r.y = f2tf(x - __uint_as_float(r.x)); return r;
}
__device__ __forceinline__ void mma8(float* c, const uint32_t* a, const uint32_t* b) {
    asm volatile(
        "mma.sync.aligned.m16n8k8.row.col.f32.tf32.tf32.f32 "
        "{%0,%1,%2,%3},{%4,%5,%6,%7},{%8,%9},{%0,%1,%2,%3};"
        : "+f"(c[0]), "+f"(c[1]), "+f"(c[2]), "+f"(c[3])
        : "r"(a[0]), "r"(a[1]), "r"(a[2]), "r"(a[3]), "r"(b[0]), "r"(b[1]));
}

// ---------------------------------------------------------------------------
// QKV GEMM: X[4096,1024] @ W[1024,3072] + bias; pre-split (hi,lo) smem.
// Block 128x128, BK=16, 8 warps (4M x 2N), warp 32x64.
// ---------------------------------------------------------------------------
__global__ __launch_bounds__(256, 2) void qkv_kernel(const float* __restrict__ X,
                                                     const float* __restrict__ W,
                                                     const float* __restrict__ bias) {
    __shared__ uint2 As[128 * 20];   // [m][k] (hi,lo)
    __shared__ uint2 Bs[16 * 132];   // [k][n]
    const int tid = threadIdx.x;
    const int lane = tid & 31, warp = tid >> 5;
    const int g = lane >> 2, t = lane & 3;
    const int wm = (warp & 3) * 32, wn = (warp >> 2) * 64;
    const int m0 = blockIdx.y * 128, n0 = blockIdx.x * 128;

    float c[2][8][4];
#pragma unroll
    for (int mi = 0; mi < 2; mi++)
#pragma unroll
        for (int jj = 0; jj < 8; jj++)
#pragma unroll
            for (int e = 0; e < 4; e++) c[mi][jj][e] = 0.f;

    float4 ra[2], rb[2];
#pragma unroll
    for (int i = 0; i < 2; i++) {
        int f = tid + i * 256, m = f >> 2, q = f & 3;
        ra[i] = *(const float4*)&X[(size_t)(m0 + m) * DMODEL + 4 * q];
    }
#pragma unroll
    for (int i = 0; i < 2; i++) {
        int f = tid + i * 256, r = f >> 5, c4 = (f & 31) * 4;
        rb[i] = *(const float4*)&W[(size_t)r * D3 + n0 + c4];
    }

    for (int k0 = 0; k0 < DMODEL; k0 += 16) {
#pragma unroll
        for (int i = 0; i < 2; i++) {
            int f = tid + i * 256, m = f >> 2, q = f & 3;
            uint2* p = &As[m * 20 + 4 * q];
            p[0] = split2(ra[i].x); p[1] = split2(ra[i].y);
            p[2] = split2(ra[i].z); p[3] = split2(ra[i].w);
        }
#pragma unroll
        for (int i = 0; i < 2; i++) {
            int f = tid + i * 256, r = f >> 5, c4 = (f & 31) * 4;
            uint2* p = &Bs[r * 132 + c4];
            p[0] = split2(rb[i].x); p[1] = split2(rb[i].y);
            p[2] = split2(rb[i].z); p[3] = split2(rb[i].w);
        }
        __syncthreads();

        if (k0 + 16 < DMODEL) {
#pragma unroll
            for (int i = 0; i < 2; i++) {
                int f = tid + i * 256, m = f >> 2, q = f & 3;
                ra[i] = *(const float4*)&X[(size_t)(m0 + m) * DMODEL + k0 + 16 + 4 * q];
            }
#pragma unroll
            for (int i = 0; i < 2; i++) {
                int f = tid + i * 256, r = f >> 5, c4 = (f & 31) * 4;
                rb[i] = *(const float4*)&W[(size_t)(k0 + 16 + r) * D3 + n0 + c4];
            }
        }

#pragma unroll
        for (int kk = 0; kk < 16; kk += 8) {
            uint32_t ah[2][4], al[2][4];
#pragma unroll
            for (int mi = 0; mi < 2; mi++) {
                int r0 = wm + mi * 16 + g;
                uint2 v0 = As[r0 * 20 + kk + t];
                uint2 v1 = As[(r0 + 8) * 20 + kk + t];
                uint2 v2 = As[r0 * 20 + kk + t + 4];
                uint2 v3 = As[(r0 + 8) * 20 + kk + t + 4];
                ah[mi][0] = v0.x; ah[mi][1] = v1.x; ah[mi][2] = v2.x; ah[mi][3] = v3.x;
                al[mi][0] = v0.y; al[mi][1] = v1.y; al[mi][2] = v2.y; al[mi][3] = v3.y;
            }
#pragma unroll
            for (int jj = 0; jj < 8; jj++) {
                int nn = wn + jj * 8 + g;
                uint2 w0 = Bs[(kk + t) * 132 + nn];
                uint2 w1 = Bs[(kk + t + 4) * 132 + nn];
                uint32_t bh[2] = {w0.x, w1.x}, bl[2] = {w0.y, w1.y};
#pragma unroll
                for (int mi = 0; mi < 2; mi++) {
                    mma8(c[mi][jj], ah[mi], bh);
                    mma8(c[mi][jj], al[mi], bh);
                    mma8(c[mi][jj], ah[mi], bl);
                }
            }
        }
        __syncthreads();
    }

#pragma unroll
    for (int mi = 0; mi < 2; mi++)
#pragma unroll
        for (int jj = 0; jj < 8; jj++)
#pragma unroll
            for (int e = 0; e < 4; e++) {
                int row = m0 + wm + mi * 16 + g + ((e >= 2) ? 8 : 0);
                int col = n0 + wn + jj * 8 + 2 * t + (e & 1);
                float v = c[mi][jj][e] + bias[col];
                int bb = row >> 11;
                int s  = row & (SEQ - 1);
                int h  = col / 192;
                int w  = col - h * 192;
                if (w < 64)
                    g_Q[((size_t)(bb * NHEAD + h) * SEQ + s) * HDIM + w] = v;
                else if (w < 128)
                    g_Kt[((size_t)(bb * NHEAD + h) * HDIM + (w - 64)) * SEQ + s] = v;
                else
                    g_V[((size_t)(bb * NHEAD + h) * SEQ + s) * HDIM + (w - 128)] = v;
            }
}

// ---------------------------------------------------------------------------
// Flash attention. Block = 128 queries x (b,h). 8 warps, warp = 16 rows x 64 keys.
// All smem operands pre-split to (hi,lo) uint2.
// ---------------------------------------------------------------------------
#define ATTN_U2    (128 * 68 + 64 * 68 + 64 * 68 + 8 * 16 * 68)
#define ATTN_BYTES (ATTN_U2 * 8)

__global__ __launch_bounds__(256) void attn_kernel(const float* __restrict__ mask) {
    extern __shared__ uint2 sm2[];
    uint2* Qs = sm2;                 // [128][68]
    uint2* Ks = Qs + 128 * 68;       // [d=64][68 keys]
    uint2* Vs = Ks + 64 * 68;        // [key=64][68 d]
    uint2* Ps = Vs + 64 * 68;        // per-warp [16][68]

    const int tid = threadIdx.x, lane = tid & 31, w = tid >> 5;
    const int g = lane >> 2, t = lane & 3;
    const int b = blockIdx.z, h = blockIdx.y;
    const int q0 = blockIdx.x * 128;
    const int qrow = w * 16 + g;

    const float* Qg = g_Q  + (size_t)(b * NHEAD + h) * SEQ * HDIM;
    const float* Kg = g_Kt + (size_t)(b * NHEAD + h) * HDIM * SEQ;
    const float* Vg = g_V  + (size_t)(b * NHEAD + h) * SEQ * HDIM;
    const float* Mg = mask + (size_t)b * SEQ * SEQ;
    uint2* Pw = Ps + w * (16 * 68);

    // Stage Q once (split)
#pragma unroll
    for (int i = 0; i < 8; i++) {
        int f = tid + i * 256, m = f >> 4, q = f & 15;
        float4 v = *(const float4*)&Qg[(size_t)(q0 + m) * HDIM + 4 * q];
        uint2* p = &Qs[m * 68 + 4 * q];
        p[0] = split2(v.x); p[1] = split2(v.y); p[2] = split2(v.z); p[3] = split2(v.w);
    }

    float o[8][4];
#pragma unroll
    for (int jj = 0; jj < 8; jj++)
#pragma unroll
        for (int e = 0; e < 4; e++) o[jj][e] = 0.f;
    float m0r = -1e30f, m1r = -1e30f, l0 = 0.f, l1 = 0.f;

    // Prefetch first K/V tile
    float4 rk[4], rv[4];
#pragma unroll
    for (int i = 0; i < 4; i++) {
        int f = tid + i * 256, r = f >> 4, q = f & 15;
        rk[i] = *(const float4*)&Kg[(size_t)r * SEQ + 4 * q];
        rv[i] = *(const float4*)&Vg[(size_t)r * HDIM + 4 * q];
    }

    for (int kt = 0; kt < SEQ; kt += 64) {
        __syncthreads();   // all warps done reading Ks/Vs of previous tile
#pragma unroll
        for (int i = 0; i < 4; i++) {
            int f = tid + i * 256, r = f >> 4, q = f & 15;
            uint2* pk = &Ks[r * 68 + 4 * q];
            pk[0] = split2(rk[i].x); pk[1] = split2(rk[i].y);
            pk[2] = split2(rk[i].z); pk[3] = split2(rk[i].w);
            uint2* pv = &Vs[r * 68 + 4 * q];
            pv[0] = split2(rv[i].x); pv[1] = split2(rv[i].y);
            pv[2] = split2(rv[i].z); pv[3] = split2(rv[i].w);
        }
        __syncthreads();

        if (kt + 64 < SEQ) {
#pragma unroll
            for (int i = 0; i < 4; i++) {
                int f = tid + i * 256, r = f >> 4, q = f & 15;
                rk[i] = *(const float4*)&Kg[(size_t)r * SEQ + kt + 64 + 4 * q];
                rv[i] = *(const float4*)&Vg[(size_t)(kt + 64 + r) * HDIM + 4 * q];
            }
        }

        // Prefetch mask tile into registers
        float2 mk0[8], mk1[8];
#pragma unroll
        for (int jj = 0; jj < 8; jj++) {
            int col = kt + jj * 8 + 2 * t;
            mk0[jj] = *(const float2*)&Mg[(size_t)(q0 + qrow) * SEQ + col];
            mk1[jj] = *(const float2*)&Mg[(size_t)(q0 + qrow + 8) * SEQ + col];
        }

        // S = Q @ K^T
        float s[8][4];
#pragma unroll
        for (int jj = 0; jj < 8; jj++)
#pragma unroll
            for (int e = 0; e < 4; e++) s[jj][e] = 0.f;

#pragma unroll
        for (int kk = 0; kk < 64; kk += 8) {
            uint32_t ah[4], al[4];
            uint2 v0 = Qs[qrow * 68 + kk + t];
            uint2 v1 = Qs[(qrow + 8) * 68 + kk + t];
            uint2 v2 = Qs[qrow * 68 + kk + t + 4];
            uint2 v3 = Qs[(qrow + 8) * 68 + kk + t + 4];
            ah[0] = v0.x; ah[1] = v1.x; ah[2] = v2.x; ah[3] = v3.x;
            al[0] = v0.y; al[1] = v1.y; al[2] = v2.y; al[3] = v3.y;
#pragma unroll
            for (int jj = 0; jj < 8; jj++) {
                int nn = jj * 8 + g;
                uint2 w0 = Ks[(kk + t) * 68 + nn];
                uint2 w1 = Ks[(kk + t + 4) * 68 + nn];
                uint32_t bh[2] = {w0.x, w1.x}, bl[2] = {w0.y, w1.y};
                mma8(s[jj], ah, bh);
                mma8(s[jj], al, bh);
                mma8(s[jj], ah, bl);
            }
        }

        // softmax update
        float vm0 = -1e30f, vm1 = -1e30f;
#pragma unroll
        for (int jj = 0; jj < 8; jj++) {
            s[jj][0] = s[jj][0] * 0.125f + mk0[jj].x;
            s[jj][1] = s[jj][1] * 0.125f + mk0[jj].y;
            s[jj][2] = s[jj][2] * 0.125f + mk1[jj].x;
            s[jj][3] = s[jj][3] * 0.125f + mk1[jj].y;
            vm0 = fmaxf(vm0, fmaxf(s[jj][0], s[jj][1]));
            vm1 = fmaxf(vm1, fmaxf(s[jj][2], s[jj][3]));
        }
        vm0 = fmaxf(vm0, __shfl_xor_sync(0xffffffffu, vm0, 1));
        vm0 = fmaxf(vm0, __shfl_xor_sync(0xffffffffu, vm0, 2));
        vm1 = fmaxf(vm1, __shfl_xor_sync(0xffffffffu, vm1, 1));
        vm1 = fmaxf(vm1, __shfl_xor_sync(0xffffffffu, vm1, 2));

        float mn0 = fmaxf(m0r, vm0), mn1 = fmaxf(m1r, vm1);
        float cor0 = __expf(m0r - mn0), cor1 = __expf(m1r - mn1);
        m0r = mn0; m1r = mn1;
        float rs0 = 0.f, rs1 = 0.f;
#pragma unroll
        for (int jj = 0; jj < 8; jj++) {
            s[jj][0] = __expf(s[jj][0] - mn0);
            s[jj][1] = __expf(s[jj][1] - mn0);
            s[jj][2] = __expf(s[jj][2] - mn1);
            s[jj][3] = __expf(s[jj][3] - mn1);
            rs0 += s[jj][0] + s[jj][1];
            rs1 += s[jj][2] + s[jj][3];
        }
        rs0 += __shfl_xor_sync(0xffffffffu, rs0, 1);
        rs0 += __shfl_xor_sync(0xffffffffu, rs0, 2);
        rs1 += __shfl_xor_sync(0xffffffffu, rs1, 1);
        rs1 += __shfl_xor_sync(0xffffffffu, rs1, 2);
        l0 = l0 * cor0 + rs0;
        l1 = l1 * cor1 + rs1;
#pragma unroll
        for (int jj = 0; jj < 8; jj++) {
            o[jj][0] *= cor0; o[jj][1] *= cor0;
            o[jj][2] *= cor1; o[jj][3] *= cor1;
        }

        // Stage P split (warp-private): packed STS.128 {hi0,lo0,hi1,lo1}
#pragma unroll
        for (int jj = 0; jj < 8; jj++) {
            uint2 a0 = split2(s[jj][0]), a1 = split2(s[jj][1]);
            uint2 b0 = split2(s[jj][2]), b1 = split2(s[jj][3]);
            *(uint4*)&Pw[g * 68 + jj * 8 + 2 * t] =
                make_uint4(a0.x, a0.y, a1.x, a1.y);
            *(uint4*)&Pw[(g + 8) * 68 + jj * 8 + 2 * t] =
                make_uint4(b0.x, b0.y, b1.x, b1.y);
        }
        __syncwarp();

        // O += P @ V
#pragma unroll
        for (int kk = 0; kk < 64; kk += 8) {
            uint32_t ah[4], al[4];
            uint2 v0 = Pw[g * 68 + kk + t];
            uint2 v1 = Pw[(g + 8) * 68 + kk + t];
            uint2 v2 = Pw[g * 68 + kk + t + 4];
            uint2 v3 = Pw[(g + 8) * 68 + kk + t + 4];
            ah[0] = v0.x; ah[1] = v1.x; ah[2] = v2.x; ah[3] = v3.x;
            al[0] = v0.y; al[1] = v1.y; al[2] = v2.y; al[3] = v3.y;
#pragma unroll
            for (int jj = 0; jj < 8; jj++) {
                int nn = jj * 8 + g;
                uint2 w0 = Vs[(kk + t) * 68 + nn];
                uint2 w1 = Vs[(kk + t + 4) * 68 + nn];
                uint32_t bh[2] = {w0.x, w1.x}, bl[2] = {w0.y, w1.y};
                mma8(o[jj], ah, bh);
                mma8(o[jj], al, bh);
                mma8(o[jj], ah, bl);
            }
        }
    }

    float inv0 = 1.f / l0, inv1 = 1.f / l1;
#pragma unroll
    for (int jj = 0; jj < 8; jj++) {
        size_t r0a = (size_t)(b * SEQ + q0 + qrow) * DMODEL + h * HDIM + jj * 8 + 2 * t;
        size_t r1a = (size_t)(b * SEQ + q0 + qrow + 8) * DMODEL + h * HDIM + jj * 8 + 2 * t;
        *(float2*)&g_vals[r0a] = make_float2(o[jj][0] * inv0, o[jj][1] * inv0);
        *(float2*)&g_vals[r1a] = make_float2(o[jj][2] * inv1, o[jj][3] * inv1);
    }
}

// ---------------------------------------------------------------------------
// Output projection: g_vals[4096,1024] @ Wo[1024,1024] + bo -> out.
// ---------------------------------------------------------------------------
__global__ __launch_bounds__(256, 2) void proj_kernel(const float* __restrict__ Wo,
                                                      const float* __restrict__ bo,
                                                      float* __restrict__ out) {
    __shared__ uint2 As[128 * 20];
    __shared__ uint2 Bs[16 * 132];
    const int tid = threadIdx.x;
    const int lane = tid & 31, warp = tid >> 5;
    const int g = lane >> 2, t = lane & 3;
    const int wm = (warp & 3) * 32, wn = (warp >> 2) * 64;
    const int m0 = blockIdx.y * 128, n0 = blockIdx.x * 128;

    float c[2][8][4];
#pragma unroll
    for (int mi = 0; mi < 2; mi++)
#pragma unroll
        for (int jj = 0; jj < 8; jj++)
#pragma unroll
            for (int e = 0; e < 4; e++) c[mi][jj][e] = 0.f;

    float4 ra[2], rb[2];
#pragma unroll
    for (int i = 0; i < 2; i++) {
        int f = tid + i * 256, m = f >> 2, q = f & 3;
        ra[i] = *(const float4*)&g_vals[(size_t)(m0 + m) * DMODEL + 4 * q];
    }
#pragma unroll
    for (int i = 0; i < 2; i++) {
        int f = tid + i * 256, r = f >> 5, c4 = (f & 31) * 4;
        rb[i] = *(const float4*)&Wo[(size_t)r * DMODEL + n0 + c4];
    }

    for (int k0 = 0; k0 < DMODEL; k0 += 16) {
#pragma unroll
        for (int i = 0; i < 2; i++) {
            int f = tid + i * 256, m = f >> 2, q = f & 3;
            uint2* p = &As[m * 20 + 4 * q];
            p[0] = split2(ra[i].x); p[1] = split2(ra[i].y);
            p[2] = split2(ra[i].z); p[3] = split2(ra[i].w);
        }
#pragma unroll
        for (int i = 0; i < 2; i++) {
            int f = tid + i * 256, r = f >> 5, c4 = (f & 31) * 4;
            uint2* p = &Bs[r * 132 + c4];
            p[0] = split2(rb[i].x); p[1] = split2(rb[i].y);
            p[2] = split2(rb[i].z); p[3] = split2(rb[i].w);
        }
        __syncthreads();

        if (k0 + 16 < DMODEL) {
#pragma unroll
            for (int i = 0; i < 2; i++) {
                int f = tid + i * 256, m = f >> 2, q = f & 3;
                ra[i] = *(const float4*)&g_vals[(size_t)(m0 + m) * DMODEL + k0 + 16 + 4 * q];
            }
#pragma unroll
            for (int i = 0; i < 2; i++) {
                int f = tid + i * 256, r = f >> 5, c4 = (f & 31) * 4;
                rb[i] = *(const float4*)&Wo[(size_t)(k0 + 16 + r) * DMODEL + n0 + c4];
            }
        }

#pragma unroll
        for (int kk = 0; kk < 16; kk += 8) {
            uint32_t ah[2][4], al[2][4];
#pragma unroll
            for (int mi = 0; mi < 2; mi++) {
                int r0 = wm + mi * 16 + g;
                uint2 v0 = As[r0 * 20 + kk + t];
                uint2 v1 = As[(r0 + 8) * 20 + kk + t];
                uint2 v2 = As[r0 * 20 + kk + t + 4];
                uint2 v3 = As[(r0 + 8) * 20 + kk + t + 4];
                ah[mi][0] = v0.x; ah[mi][1] = v1.x; ah[mi][2] = v2.x; ah[mi][3] = v3.x;
                al[mi][0] = v0.y; al[mi][1] = v1.y; al[mi][2] = v2.y; al[mi][3] = v3.y;
            }
#pragma unroll
            for (int jj = 0; jj < 8; jj++) {
                int nn = wn + jj * 8 + g;
                uint2 w0 = Bs[(kk + t) * 132 + nn];
                uint2 w1 = Bs[(kk + t + 4) * 132 + nn];
                uint32_t bh[2] = {w0.x, w1.x}, bl[2] = {w0.y, w1.y};
#pragma unroll
                for (int mi = 0; mi < 2; mi++) {
                    mma8(c[mi][jj], ah[mi], bh);
                    mma8(c[mi][jj], al[mi], bh);
                    mma8(c[mi][jj], ah[mi], bl);
                }
            }
        }
        __syncthreads();
    }

#pragma unroll
    for (int mi = 0; mi < 2; mi++)
#pragma unroll
        for (int jj = 0; jj < 8; jj++) {
            int row0 = m0 + wm + mi * 16 + g;
            int col  = n0 + wn + jj * 8 + 2 * t;
            float b0 = bo[col], b1 = bo[col + 1];
            *(float2*)&out[(size_t)row0 * DMODEL + col] =
                make_float2(c[mi][jj][0] + b0, c[mi][jj][1] + b1);
            *(float2*)&out[(size_t)(row0 + 8) * DMODEL + col] =
                make_float2(c[mi][jj][2] + b0, c[mi][jj][3] + b1);
        }
}

// ---------------------------------------------------------------------------
extern "C" void kernel_launch(void* const* d_in, const int* in_sizes, int n_in,
                              void* d_out, int out_size) {
    const float* x    = (const float*)d_in[0];
    const float* mask = (const float*)d_in[1];
    const float* Wqkv = (const float*)d_in[2];
    const float* bqkv = (const float*)d_in[3];
    const float* Wo   = (const float*)d_in[4];
    const float* bo   = (const float*)d_in[5];
    float* out = (float*)d_out;

    cudaFuncSetAttribute(attn_kernel, cudaFuncAttributeMaxDynamicSharedMemorySize,
                         ATTN_BYTES);

    dim3 gq(D3 / 128, (BATCH * SEQ) / 128);
    qkv_kernel<<<gq, 256>>>(x, Wqkv, bqkv);

    dim3 ga(SEQ / 128, NHEAD, BATCH);
    attn_kernel<<<ga, 256, ATTN_BYTES>>>(mask);

    dim3 gp(DMODEL / 128, (BATCH * SEQ) / 128);
    proj_kernel<<<gp, 256>>>(Wo, bo, out);
}

// round 5
// speedup vs baseline: 1.2441x; 1.2441x over previous
#include <cuda_runtime.h>
#include <stdint.h>

#define BATCH  2
#define SEQ    2048
#define DMODEL 1024
#define NHEAD  16
#define HDIM   64
#define D3     3072

// Scratch. K stored TRANSPOSED: [B,H,HDIM,SEQ].
__device__ __align__(16) float g_Q   [BATCH * NHEAD * SEQ * HDIM];
__device__ __align__(16) float g_Kt  [BATCH * NHEAD * HDIM * SEQ];
__device__ __align__(16) float g_V   [BATCH * NHEAD * SEQ * HDIM];
__device__ __align__(16) float g_vals[BATCH * SEQ * DMODEL];

// ---- tf32 helpers ----------------------------------------------------------
__device__ __forceinline__ uint32_t f2tf(float x) {
    uint32_t u; asm("cvt.rna.tf32.f32 %0, %1;" : "=r"(u) : "f"(x)); return u;
}
__device__ __forceinline__ uint2 split2(float x) {
    uint2 r; r.x = f2tf(x); r.y = f2tf(x - __uint_as_float(r.x)); return r;
}
__device__ __forceinline__ void split_tf32(float x, uint32_t& hi, uint32_t& lo) {
    hi = f2tf(x);
    lo = f2tf(x - __uint_as_float(hi));
}
__device__ __forceinline__ void mma8(float* c, const uint32_t* a, const uint32_t* b) {
    asm volatile(
        "mma.sync.aligned.m16n8k8.row.col.f32.tf32.tf32.f32 "
        "{%0,%1,%2,%3},{%4,%5,%6,%7},{%8,%9},{%0,%1,%2,%3};"
        : "+f"(c[0]), "+f"(c[1]), "+f"(c[2]), "+f"(c[3])
        : "r"(a[0]), "r"(a[1]), "r"(a[2]), "r"(a[3]), "r"(b[0]), "r"(b[1]));
}

// GEMM smem geometry (floats)
#define AS_STRIDE 20
#define BS_STRIDE 136
#define AS_SIZE   (128 * AS_STRIDE)
#define BS_SIZE   (16 * BS_STRIDE)
#define GEMM_SMEM_FLOATS (4 * AS_SIZE + 4 * BS_SIZE)
#define GEMM_SMEM_BYTES  (GEMM_SMEM_FLOATS * 4)

// ---------------------------------------------------------------------------
// GEMM body: C[128x128] tile, BK=16, 8 warps (4M x 2N), warp 32x64.
// hi/lo pre-split planes, double-buffered smem.
// ---------------------------------------------------------------------------
template <int LDB, bool QKV>
__device__ __forceinline__ void gemm_body(const float* __restrict__ A,
                                          const float* __restrict__ B,
                                          const float* __restrict__ bias,
                                          float* __restrict__ outp,
                                          int m0, int n0, int K) {
    extern __shared__ float smf[];
    float* Ah = smf;
    float* Al = Ah + 2 * AS_SIZE;
    float* Bh = Al + 2 * AS_SIZE;
    float* Bl = Bh + 2 * BS_SIZE;

    const int tid = threadIdx.x;
    const int lane = tid & 31, warp = tid >> 5;
    const int g = lane >> 2, t = lane & 3;
    const int wm = (warp & 3) * 32, wn = (warp >> 2) * 64;

    float c[2][8][4];
#pragma unroll
    for (int mi = 0; mi < 2; mi++)
#pragma unroll
        for (int jj = 0; jj < 8; jj++)
#pragma unroll
            for (int e = 0; e < 4; e++) c[mi][jj][e] = 0.f;

    const int am  = tid >> 2,          aq = (tid & 3) * 4;
    const int am2 = (tid + 256) >> 2;
    const int br  = tid >> 5,          bc = (tid & 31) * 4;
    const int br2 = (tid + 256) >> 5;

    float4 ra[2], rb[2];
    ra[0] = *(const float4*)&A[(size_t)(m0 + am) * K + aq];
    ra[1] = *(const float4*)&A[(size_t)(m0 + am2) * K + aq];
    rb[0] = *(const float4*)&B[(size_t)br * LDB + n0 + bc];
    rb[1] = *(const float4*)&B[(size_t)br2 * LDB + n0 + bc];

    // stage buffer 0
    {
        uint2 s0, s1, s2, s3;
#pragma unroll
        for (int i = 0; i < 2; i++) {
            int m = i ? am2 : am;
            s0 = split2(ra[i].x); s1 = split2(ra[i].y);
            s2 = split2(ra[i].z); s3 = split2(ra[i].w);
            *(float4*)&Ah[m * AS_STRIDE + aq] = make_float4(
                __uint_as_float(s0.x), __uint_as_float(s1.x),
                __uint_as_float(s2.x), __uint_as_float(s3.x));
            *(float4*)&Al[m * AS_STRIDE + aq] = make_float4(
                __uint_as_float(s0.y), __uint_as_float(s1.y),
                __uint_as_float(s2.y), __uint_as_float(s3.y));
        }
#pragma unroll
        for (int i = 0; i < 2; i++) {
            int r = i ? br2 : br;
            s0 = split2(rb[i].x); s1 = split2(rb[i].y);
            s2 = split2(rb[i].z); s3 = split2(rb[i].w);
            *(float4*)&Bh[r * BS_STRIDE + bc] = make_float4(
                __uint_as_float(s0.x), __uint_as_float(s1.x),
                __uint_as_float(s2.x), __uint_as_float(s3.x));
            *(float4*)&Bl[r * BS_STRIDE + bc] = make_float4(
                __uint_as_float(s0.y), __uint_as_float(s1.y),
                __uint_as_float(s2.y), __uint_as_float(s3.y));
        }
    }

    int cur = 0;
    for (int k0 = 0; k0 < K; k0 += 16) {
        __syncthreads();
        const bool more = (k0 + 16) < K;
        if (more) {
            ra[0] = *(const float4*)&A[(size_t)(m0 + am) * K + k0 + 16 + aq];
            ra[1] = *(const float4*)&A[(size_t)(m0 + am2) * K + k0 + 16 + aq];
            rb[0] = *(const float4*)&B[(size_t)(k0 + 16 + br) * LDB + n0 + bc];
            rb[1] = *(const float4*)&B[(size_t)(k0 + 16 + br2) * LDB + n0 + bc];
        }

        const float* cAh = Ah + cur * AS_SIZE;
        const float* cAl = Al + cur * AS_SIZE;
        const float* cBh = Bh + cur * BS_SIZE;
        const float* cBl = Bl + cur * BS_SIZE;

#pragma unroll
        for (int kk = 0; kk < 16; kk += 8) {
            uint32_t ah[2][4], al[2][4];
#pragma unroll
            for (int mi = 0; mi < 2; mi++) {
                int r0 = wm + mi * 16 + g;
                ah[mi][0] = __float_as_uint(cAh[r0 * AS_STRIDE + kk + t]);
                ah[mi][1] = __float_as_uint(cAh[(r0 + 8) * AS_STRIDE + kk + t]);
                ah[mi][2] = __float_as_uint(cAh[r0 * AS_STRIDE + kk + t + 4]);
                ah[mi][3] = __float_as_uint(cAh[(r0 + 8) * AS_STRIDE + kk + t + 4]);
                al[mi][0] = __float_as_uint(cAl[r0 * AS_STRIDE + kk + t]);
                al[mi][1] = __float_as_uint(cAl[(r0 + 8) * AS_STRIDE + kk + t]);
                al[mi][2] = __float_as_uint(cAl[r0 * AS_STRIDE + kk + t + 4]);
                al[mi][3] = __float_as_uint(cAl[(r0 + 8) * AS_STRIDE + kk + t + 4]);
            }
#pragma unroll
            for (int jj = 0; jj < 8; jj++) {
                int nn = wn + jj * 8 + g;
                uint32_t bh[2], bl[2];
                bh[0] = __float_as_uint(cBh[(kk + t) * BS_STRIDE + nn]);
                bh[1] = __float_as_uint(cBh[(kk + t + 4) * BS_STRIDE + nn]);
                bl[0] = __float_as_uint(cBl[(kk + t) * BS_STRIDE + nn]);
                bl[1] = __float_as_uint(cBl[(kk + t + 4) * BS_STRIDE + nn]);
#pragma unroll
                for (int mi = 0; mi < 2; mi++) {
                    mma8(c[mi][jj], ah[mi], bh);
                    mma8(c[mi][jj], al[mi], bh);
                    mma8(c[mi][jj], ah[mi], bl);
                }
            }
        }

        if (more) {
            float* nAh = Ah + (cur ^ 1) * AS_SIZE;
            float* nAl = Al + (cur ^ 1) * AS_SIZE;
            float* nBh = Bh + (cur ^ 1) * BS_SIZE;
            float* nBl = Bl + (cur ^ 1) * BS_SIZE;
            uint2 s0, s1, s2, s3;
#pragma unroll
            for (int i = 0; i < 2; i++) {
                int m = i ? am2 : am;
                s0 = split2(ra[i].x); s1 = split2(ra[i].y);
                s2 = split2(ra[i].z); s3 = split2(ra[i].w);
                *(float4*)&nAh[m * AS_STRIDE + aq] = make_float4(
                    __uint_as_float(s0.x), __uint_as_float(s1.x),
                    __uint_as_float(s2.x), __uint_as_float(s3.x));
                *(float4*)&nAl[m * AS_STRIDE + aq] = make_float4(
                    __uint_as_float(s0.y), __uint_as_float(s1.y),
                    __uint_as_float(s2.y), __uint_as_float(s3.y));
            }
#pragma unroll
            for (int i = 0; i < 2; i++) {
                int r = i ? br2 : br;
                s0 = split2(rb[i].x); s1 = split2(rb[i].y);
                s2 = split2(rb[i].z); s3 = split2(rb[i].w);
                *(float4*)&nBh[r * BS_STRIDE + bc] = make_float4(
                    __uint_as_float(s0.x), __uint_as_float(s1.x),
                    __uint_as_float(s2.x), __uint_as_float(s3.x));
                *(float4*)&nBl[r * BS_STRIDE + bc] = make_float4(
                    __uint_as_float(s0.y), __uint_as_float(s1.y),
                    __uint_as_float(s2.y), __uint_as_float(s3.y));
            }
        }
        cur ^= 1;
    }

#pragma unroll
    for (int mi = 0; mi < 2; mi++)
#pragma unroll
        for (int jj = 0; jj < 8; jj++)
#pragma unroll
            for (int e = 0; e < 4; e++) {
                int row = m0 + wm + mi * 16 + g + ((e >= 2) ? 8 : 0);
                int col = n0 + wn + jj * 8 + 2 * t + (e & 1);
                float v = c[mi][jj][e] + bias[col];
                if (QKV) {
                    int bb = row >> 11;
                    int s  = row & (SEQ - 1);
                    int h  = col / 192;
                    int w  = col - h * 192;
                    if (w < 64)
                        g_Q[((size_t)(bb * NHEAD + h) * SEQ + s) * HDIM + w] = v;
                    else if (w < 128)
                        g_Kt[((size_t)(bb * NHEAD + h) * HDIM + (w - 64)) * SEQ + s] = v;
                    else
                        g_V[((size_t)(bb * NHEAD + h) * SEQ + s) * HDIM + (w - 128)] = v;
                } else {
                    outp[(size_t)row * DMODEL + col] = v;
                }
            }
}

__global__ __launch_bounds__(256, 2) void qkv_kernel(const float* __restrict__ X,
                                                     const float* __restrict__ W,
                                                     const float* __restrict__ bias) {
    gemm_body<D3, true>(X, W, bias, nullptr, blockIdx.y * 128, blockIdx.x * 128, DMODEL);
}

__global__ __launch_bounds__(256, 2) void proj_kernel(const float* __restrict__ Wo,
                                                      const float* __restrict__ bo,
                                                      float* __restrict__ out) {
    gemm_body<DMODEL, false>(g_vals, Wo, bo, out, blockIdx.y * 128, blockIdx.x * 128, DMODEL);
}

// ---------------------------------------------------------------------------
// Flash attention — EXACT R2 version (1446us config). Block = 128 q x (b,h).
// 8 warps, warp = 16 rows x 64 keys. Split at fragment load; P staged float2.
// ---------------------------------------------------------------------------
#define ATTN_SMEM_FLOATS (128 * 68 + 64 * 72 + 64 * 72 + 8 * 16 * 72)
#define ATTN_BYTES       (ATTN_SMEM_FLOATS * 4)

__global__ __launch_bounds__(256) void attn_kernel(const float* __restrict__ mask) {
    extern __shared__ float sm[];
    float* Qs = sm;                       // [128][68]
    float* Ks = Qs + 128 * 68;            // [d][key] stride 72
    float* Vs = Ks + 64 * 72;             // [key][d] stride 72
    float* Ps = Vs + 64 * 72;             // per-warp [16][72]

    const int tid = threadIdx.x, lane = tid & 31, w = tid >> 5;
    const int g = lane >> 2, t = lane & 3;
    const int b = blockIdx.z, h = blockIdx.y;
    const int q0 = blockIdx.x * 128;
    const int qrow = w * 16 + g;

    const float* Qg = g_Q  + (size_t)(b * NHEAD + h) * SEQ * HDIM;
    const float* Kg = g_Kt + (size_t)(b * NHEAD + h) * HDIM * SEQ;
    const float* Vg = g_V  + (size_t)(b * NHEAD + h) * SEQ * HDIM;
    const float* Mg = mask + (size_t)b * SEQ * SEQ;
    float* Pw = Ps + w * (16 * 72);

#pragma unroll
    for (int i = 0; i < 8; i++) {
        int f = tid + i * 256;
        int m = f >> 4, q = f & 15;
        *(float4*)&Qs[m * 68 + 4 * q] =
            *(const float4*)&Qg[(size_t)(q0 + m) * HDIM + 4 * q];
    }

    float o[8][4];
#pragma unroll
    for (int jj = 0; jj < 8; jj++)
#pragma unroll
        for (int e = 0; e < 4; e++) o[jj][e] = 0.f;
    float m0r = -1e30f, m1r = -1e30f, l0 = 0.f, l1 = 0.f;

    float4 rk[4], rv[4];
#pragma unroll
    for (int i = 0; i < 4; i++) {
        int f = tid + i * 256, r = f >> 4, q = f & 15;
        rk[i] = *(const float4*)&Kg[(size_t)r * SEQ + 4 * q];
        rv[i] = *(const float4*)&Vg[(size_t)r * HDIM + 4 * q];
    }

    for (int kt = 0; kt < SEQ; kt += 64) {
        __syncthreads();
#pragma unroll
        for (int i = 0; i < 4; i++) {
            int f = tid + i * 256, r = f >> 4, q = f & 15;
            *(float4*)&Ks[r * 72 + 4 * q] = rk[i];
            *(float4*)&Vs[r * 72 + 4 * q] = rv[i];
        }
        __syncthreads();

        if (kt + 64 < SEQ) {
#pragma unroll
            for (int i = 0; i < 4; i++) {
                int f = tid + i * 256, r = f >> 4, q = f & 15;
                rk[i] = *(const float4*)&Kg[(size_t)r * SEQ + kt + 64 + 4 * q];
                rv[i] = *(const float4*)&Vg[(size_t)(kt + 64 + r) * HDIM + 4 * q];
            }
        }

        float2 mk0[8], mk1[8];
#pragma unroll
        for (int jj = 0; jj < 8; jj++) {
            int col = kt + jj * 8 + 2 * t;
            mk0[jj] = *(const float2*)&Mg[(size_t)(q0 + qrow) * SEQ + col];
            mk1[jj] = *(const float2*)&Mg[(size_t)(q0 + qrow + 8) * SEQ + col];
        }

        float s[8][4];
#pragma unroll
        for (int jj = 0; jj < 8; jj++)
#pragma unroll
            for (int e = 0; e < 4; e++) s[jj][e] = 0.f;

#pragma unroll
        for (int kk = 0; kk < 64; kk += 8) {
            uint32_t ah[4], al[4];
            split_tf32(Qs[qrow * 68 + kk + t],           ah[0], al[0]);
            split_tf32(Qs[(qrow + 8) * 68 + kk + t],     ah[1], al[1]);
            split_tf32(Qs[qrow * 68 + kk + t + 4],       ah[2], al[2]);
            split_tf32(Qs[(qrow + 8) * 68 + kk + t + 4], ah[3], al[3]);
#pragma unroll
            for (int jj = 0; jj < 8; jj++) {
                uint32_t bh[2], bl[2];
                int nn = jj * 8 + g;
                split_tf32(Ks[(kk + t) * 72 + nn],     bh[0], bl[0]);
                split_tf32(Ks[(kk + t + 4) * 72 + nn], bh[1], bl[1]);
                mma8(s[jj], ah, bh);
                mma8(s[jj], ah, bl);
                mma8(s[jj], al, bh);
            }
        }

        float vm0 = -1e30f, vm1 = -1e30f;
#pragma unroll
        for (int jj = 0; jj < 8; jj++) {
            s[jj][0] = s[jj][0] * 0.125f + mk0[jj].x;
            s[jj][1] = s[jj][1] * 0.125f + mk0[jj].y;
            s[jj][2] = s[jj][2] * 0.125f + mk1[jj].x;
            s[jj][3] = s[jj][3] * 0.125f + mk1[jj].y;
            vm0 = fmaxf(vm0, fmaxf(s[jj][0], s[jj][1]));
            vm1 = fmaxf(vm1, fmaxf(s[jj][2], s[jj][3]));
        }
        vm0 = fmaxf(vm0, __shfl_xor_sync(0xffffffffu, vm0, 1));
        vm0 = fmaxf(vm0, __shfl_xor_sync(0xffffffffu, vm0, 2));
        vm1 = fmaxf(vm1, __shfl_xor_sync(0xffffffffu, vm1, 1));
        vm1 = fmaxf(vm1, __shfl_xor_sync(0xffffffffu, vm1, 2));

        float mn0 = fmaxf(m0r, vm0), mn1 = fmaxf(m1r, vm1);
        float cor0 = __expf(m0r - mn0), cor1 = __expf(m1r - mn1);
        m0r = mn0; m1r = mn1;
        float rs0 = 0.f, rs1 = 0.f;
#pragma unroll
        for (int jj = 0; jj < 8; jj++) {
            s[jj][0] = __expf(s[jj][0] - mn0);
            s[jj][1] = __expf(s[jj][1] - mn0);
            s[jj][2] = __expf(s[jj][2] - mn1);
            s[jj][3] = __expf(s[jj][3] - mn1);
            rs0 += s[jj][0] + s[jj][1];
            rs1 += s[jj][2] + s[jj][3];
        }
        rs0 += __shfl_xor_sync(0xffffffffu, rs0, 1);
        rs0 += __shfl_xor_sync(0xffffffffu, rs0, 2);
        rs1 += __shfl_xor_sync(0xffffffffu, rs1, 1);
        rs1 += __shfl_xor_sync(0xffffffffu, rs1, 2);
        l0 = l0 * cor0 + rs0;
        l1 = l1 * cor1 + rs1;
#pragma unroll
        for (int jj = 0; jj < 8; jj++) {
            o[jj][0] *= cor0; o[jj][1] *= cor0;
            o[jj][2] *= cor1; o[jj][3] *= cor1;
        }

        // Stage P (per-warp region, float2 stores — 8B aligned, legal)
#pragma unroll
        for (int jj = 0; jj < 8; jj++) {
            *(float2*)&Pw[g * 72 + jj * 8 + 2 * t]       = make_float2(s[jj][0], s[jj][1]);
            *(float2*)&Pw[(g + 8) * 72 + jj * 8 + 2 * t] = make_float2(s[jj][2], s[jj][3]);
        }
        __syncwarp();

        // O += P @ V
#pragma unroll
        for (int kk = 0; kk < 64; kk += 8) {
            uint32_t ah[4], al[4];
            split_tf32(Pw[g * 72 + kk + t],           ah[0], al[0]);
            split_tf32(Pw[(g + 8) * 72 + kk + t],     ah[1], al[1]);
            split_tf32(Pw[g * 72 + kk + t + 4],       ah[2], al[2]);
            split_tf32(Pw[(g + 8) * 72 + kk + t + 4], ah[3], al[3]);
#pragma unroll
            for (int jj = 0; jj < 8; jj++) {
                uint32_t bh[2], bl[2];
                int nn = jj * 8 + g;
                split_tf32(Vs[(kk + t) * 72 + nn],     bh[0], bl[0]);
                split_tf32(Vs[(kk + t + 4) * 72 + nn], bh[1], bl[1]);
                mma8(o[jj], ah, bh);
                mma8(o[jj], ah, bl);
                mma8(o[jj], al, bh);
            }
        }
        __syncwarp();
    }

    float inv0 = 1.f / l0, inv1 = 1.f / l1;
#pragma unroll
    for (int jj = 0; jj < 8; jj++) {
        size_t r0a = (size_t)(b * SEQ + q0 + qrow) * DMODEL + h * HDIM + jj * 8 + 2 * t;
        size_t r1a = (size_t)(b * SEQ + q0 + qrow + 8) * DMODEL + h * HDIM + jj * 8 + 2 * t;
        *(float2*)&g_vals[r0a] = make_float2(o[jj][0] * inv0, o[jj][1] * inv0);
        *(float2*)&g_vals[r1a] = make_float2(o[jj][2] * inv1, o[jj][3] * inv1);
    }
}

// ---------------------------------------------------------------------------
extern "C" void kernel_launch(void* const* d_in, const int* in_sizes, int n_in,
                              void* d_out, int out_size) {
    const float* x    = (const float*)d_in[0];
    const float* mask = (const float*)d_in[1];
    const float* Wqkv = (const float*)d_in[2];
    const float* bqkv = (const float*)d_in[3];
    const float* Wo   = (const float*)d_in[4];
    const float* bo   = (const float*)d_in[5];
    float* out = (float*)d_out;

    cudaFuncSetAttribute(qkv_kernel, cudaFuncAttributeMaxDynamicSharedMemorySize,
                         GEMM_SMEM_BYTES);
    cudaFuncSetAttribute(proj_kernel, cudaFuncAttributeMaxDynamicSharedMemorySize,
                         GEMM_SMEM_BYTES);
    cudaFuncSetAttribute(attn_kernel, cudaFuncAttributeMaxDynamicSharedMemorySize,
                         ATTN_BYTES);

    dim3 gq(D3 / 128, (BATCH * SEQ) / 128);
    qkv_kernel<<<gq, 256, GEMM_SMEM_BYTES>>>(x, Wqkv, bqkv);

    dim3 ga(SEQ / 128, NHEAD, BATCH);
    attn_kernel<<<ga, 256, ATTN_BYTES>>>(mask);

    dim3 gp(DMODEL / 128, (BATCH * SEQ) / 128);
    proj_kernel<<<gp, 256, GEMM_SMEM_BYTES>>>(Wo, bo, out);
}

// round 6
// speedup vs baseline: 2.3846x; 1.9167x over previous
#include <cuda_runtime.h>
#include <cuda_fp16.h>
#include <stdint.h>

#define BATCH  2
#define SEQ    2048
#define DMODEL 1024
#define NHEAD  16
#define HDIM   64
#define D3     3072

// Scratch: Q/K/V natural [B,H,S,hd]; vals [B,S,D]
__device__ __align__(16) float g_Q   [BATCH * NHEAD * SEQ * HDIM];
__device__ __align__(16) float g_K   [BATCH * NHEAD * SEQ * HDIM];
__device__ __align__(16) float g_V   [BATCH * NHEAD * SEQ * HDIM];
__device__ __align__(16) float g_vals[BATCH * SEQ * DMODEL];

// ---- fp16 helpers ----------------------------------------------------------
// Pack (a,b) as half2 (a in low 16 bits = smaller k index) with hi/lo split:
// hi word = (h(a), h(b)); lo word = (h(a-hi_a), h(b-hi_b)).
__device__ __forceinline__ void h2split(float a, float b, uint32_t& hi, uint32_t& lo) {
    __half2 h = __floats2half2_rn(a, b);
    float2 f = __half22float2(h);
    __half2 l = __floats2half2_rn(a - f.x, b - f.y);
    hi = *(uint32_t*)&h;
    lo = *(uint32_t*)&l;
}
__device__ __forceinline__ void mma16(float* c, const uint32_t* a, const uint32_t* b) {
    asm volatile(
        "mma.sync.aligned.m16n8k16.row.col.f32.f16.f16.f32 "
        "{%0,%1,%2,%3},{%4,%5,%6,%7},{%8,%9},{%0,%1,%2,%3};"
        : "+f"(c[0]), "+f"(c[1]), "+f"(c[2]), "+f"(c[3])
        : "r"(a[0]), "r"(a[1]), "r"(a[2]), "r"(a[3]), "r"(b[0]), "r"(b[1]));
}

// GEMM smem geometry (32-bit half2 words)
#define GA_W   12                  // A row stride: 8 k-words + 4 pad (banks 12g+t distinct)
#define GB_W   136                 // B pair-row stride: 128 + 8 (banks 8t+g distinct)
#define GA_SZ  (128 * GA_W)        // 1536 words / plane / buffer
#define GB_SZ  (8 * GB_W)          // 1088 words
#define GEMM_WORDS (4 * GA_SZ + 4 * GB_SZ)
#define GEMM_BYTES (GEMM_WORDS * 4)

// ---------------------------------------------------------------------------
// GEMM: C[128x128] tile, BK=16 (one k16 chunk), 8 warps (4M x 2N), warp 32x64.
// fp16 hi/lo planes, double-buffered, register-prefetched staging.
// ---------------------------------------------------------------------------
template <int LDB, bool QKV>
__device__ __forceinline__ void gemm_body(const float* __restrict__ A,
                                          const float* __restrict__ B,
                                          const float* __restrict__ bias,
                                          float* __restrict__ outp,
                                          int m0, int n0, int K) {
    extern __shared__ uint32_t smw[];
    uint32_t* Ah = smw;
    uint32_t* Al = Ah + 2 * GA_SZ;
    uint32_t* Bh = Al + 2 * GA_SZ;
    uint32_t* Bl = Bh + 2 * GB_SZ;

    const int tid = threadIdx.x;
    const int lane = tid & 31, warp = tid >> 5;
    const int g = lane >> 2, t = lane & 3;
    const int wm = (warp & 3) * 32, wn = (warp >> 2) * 64;

    float c[2][8][4];
#pragma unroll
    for (int mi = 0; mi < 2; mi++)
#pragma unroll
        for (int jj = 0; jj < 8; jj++)
#pragma unroll
            for (int e = 0; e < 4; e++) c[mi][jj][e] = 0.f;

    // staging geometry: A: row am, 8 floats at col 8*ah; B: k-pair bp, 4 cols at bc
    const int am = tid >> 1, ah = tid & 1;
    const int bp = tid >> 5, bc = (tid & 31) * 4;

    float4 ra0, ra1, rb0, rb1;
    ra0 = *(const float4*)&A[(size_t)(m0 + am) * K + 8 * ah];
    ra1 = *(const float4*)&A[(size_t)(m0 + am) * K + 8 * ah + 4];
    rb0 = *(const float4*)&B[(size_t)(2 * bp) * LDB + n0 + bc];
    rb1 = *(const float4*)&B[(size_t)(2 * bp + 1) * LDB + n0 + bc];

#define GEMM_STAGE(buf)                                                        \
    {                                                                          \
        uint32_t w0h, w0l, w1h, w1l, w2h, w2l, w3h, w3l;                       \
        h2split(ra0.x, ra0.y, w0h, w0l); h2split(ra0.z, ra0.w, w1h, w1l);      \
        h2split(ra1.x, ra1.y, w2h, w2l); h2split(ra1.z, ra1.w, w3h, w3l);      \
        *(uint4*)&Ah[(buf) * GA_SZ + am * GA_W + 4 * ah] =                     \
            make_uint4(w0h, w1h, w2h, w3h);                                    \
        *(uint4*)&Al[(buf) * GA_SZ + am * GA_W + 4 * ah] =                     \
            make_uint4(w0l, w1l, w2l, w3l);                                    \
        h2split(rb0.x, rb1.x, w0h, w0l); h2split(rb0.y, rb1.y, w1h, w1l);      \
        h2split(rb0.z, rb1.z, w2h, w2l); h2split(rb0.w, rb1.w, w3h, w3l);      \
        *(uint4*)&Bh[(buf) * GB_SZ + bp * GB_W + bc] =                         \
            make_uint4(w0h, w1h, w2h, w3h);                                    \
        *(uint4*)&Bl[(buf) * GB_SZ + bp * GB_W + bc] =                         \
            make_uint4(w0l, w1l, w2l, w3l);                                    \
    }

    GEMM_STAGE(0);

    int cur = 0;
    for (int k0 = 0; k0 < K; k0 += 16) {
        __syncthreads();
        const bool more = (k0 + 16) < K;
        if (more) {
            ra0 = *(const float4*)&A[(size_t)(m0 + am) * K + k0 + 16 + 8 * ah];
            ra1 = *(const float4*)&A[(size_t)(m0 + am) * K + k0 + 16 + 8 * ah + 4];
            rb0 = *(const float4*)&B[(size_t)(k0 + 16 + 2 * bp) * LDB + n0 + bc];
            rb1 = *(const float4*)&B[(size_t)(k0 + 16 + 2 * bp + 1) * LDB + n0 + bc];
        }

        const uint32_t* cAh = Ah + cur * GA_SZ;
        const uint32_t* cAl = Al + cur * GA_SZ;
        const uint32_t* cBh = Bh + cur * GB_SZ;
        const uint32_t* cBl = Bl + cur * GB_SZ;

        uint32_t fah[2][4], fal[2][4];
#pragma unroll
        for (int mi = 0; mi < 2; mi++) {
            int r0 = wm + mi * 16 + g;
            fah[mi][0] = cAh[r0 * GA_W + t];
            fah[mi][1] = cAh[(r0 + 8) * GA_W + t];
            fah[mi][2] = cAh[r0 * GA_W + 4 + t];
            fah[mi][3] = cAh[(r0 + 8) * GA_W + 4 + t];
            fal[mi][0] = cAl[r0 * GA_W + t];
            fal[mi][1] = cAl[(r0 + 8) * GA_W + t];
            fal[mi][2] = cAl[r0 * GA_W + 4 + t];
            fal[mi][3] = cAl[(r0 + 8) * GA_W + 4 + t];
        }
#pragma unroll
        for (int jj = 0; jj < 8; jj++) {
            int nn = wn + jj * 8 + g;
            uint32_t bh[2], bl[2];
            bh[0] = cBh[t * GB_W + nn];
            bh[1] = cBh[(4 + t) * GB_W + nn];
            bl[0] = cBl[t * GB_W + nn];
            bl[1] = cBl[(4 + t) * GB_W + nn];
#pragma unroll
            for (int mi = 0; mi < 2; mi++) {
                mma16(c[mi][jj], fah[mi], bh);
                mma16(c[mi][jj], fal[mi], bh);
                mma16(c[mi][jj], fah[mi], bl);
            }
        }

        if (more) GEMM_STAGE(cur ^ 1);
        cur ^= 1;
    }

#pragma unroll
    for (int mi = 0; mi < 2; mi++)
#pragma unroll
        for (int jj = 0; jj < 8; jj++)
#pragma unroll
            for (int e = 0; e < 4; e++) {
                int row = m0 + wm + mi * 16 + g + ((e >= 2) ? 8 : 0);
                int col = n0 + wn + jj * 8 + 2 * t + (e & 1);
                float v = c[mi][jj][e] + bias[col];
                if (QKV) {
                    int bb = row >> 11;
                    int s  = row & (SEQ - 1);
                    int h  = col / 192;
                    int w  = col - h * 192;
                    size_t base = ((size_t)(bb * NHEAD + h) * SEQ + s) * HDIM;
                    if (w < 64)       g_Q[base + w]        = v;
                    else if (w < 128) g_K[base + (w - 64)] = v;
                    else              g_V[base + (w - 128)] = v;
                } else {
                    outp[(size_t)row * DMODEL + col] = v;
                }
            }
}

__global__ __launch_bounds__(256, 2) void qkv_kernel(const float* __restrict__ X,
                                                     const float* __restrict__ W,
                                                     const float* __restrict__ bias) {
    gemm_body<D3, true>(X, W, bias, nullptr, blockIdx.y * 128, blockIdx.x * 128, DMODEL);
}

__global__ __launch_bounds__(256, 2) void proj_kernel(const float* __restrict__ Wo,
                                                      const float* __restrict__ bo,
                                                      float* __restrict__ out) {
    gemm_body<DMODEL, false>(g_vals, Wo, bo, out, blockIdx.y * 128, blockIdx.x * 128, DMODEL);
}

// ---------------------------------------------------------------------------
// Flash attention, fp16 3-term. Block = 128 q x (b,h). 8 warps, warp 16 q-rows.
// Q/K/V hi-lo half2 planes in smem; P fragments live in registers (no staging).
// ---------------------------------------------------------------------------
#define AQ_W 36    // Q row stride words (32 + 4)   banks 4g+t
#define AK_W 36    // K row stride words (32 + 4)   banks 4g+t
#define AV_W 72    // V pair-row stride words (64+8) banks 8t+g
#define ATTN_WORDS (2 * 128 * AQ_W + 2 * 64 * AK_W + 2 * 32 * AV_W)
#define ATTN_BYTES (ATTN_WORDS * 4)

__global__ __launch_bounds__(256, 2) void attn_kernel(const float* __restrict__ mask) {
    extern __shared__ uint32_t smw[];
    uint32_t* Qh = smw;
    uint32_t* Ql = Qh + 128 * AQ_W;
    uint32_t* Kh = Ql + 128 * AQ_W;
    uint32_t* Kl = Kh + 64 * AK_W;
    uint32_t* Vh = Kl + 64 * AK_W;
    uint32_t* Vl = Vh + 32 * AV_W;

    const int tid = threadIdx.x, lane = tid & 31, w = tid >> 5;
    const int g = lane >> 2, t = lane & 3;
    const int b = blockIdx.z, h = blockIdx.y;
    const int q0 = blockIdx.x * 128;
    const int qrow = w * 16 + g;

    const float* Qg = g_Q + (size_t)(b * NHEAD + h) * SEQ * HDIM;
    const float* Kg = g_K + (size_t)(b * NHEAD + h) * SEQ * HDIM;
    const float* Vg = g_V + (size_t)(b * NHEAD + h) * SEQ * HDIM;
    const float* Mg = mask + (size_t)b * SEQ * SEQ;

    // ---- stage Q once: row m = tid/2, cols 32*(tid&1).. (+31)
    {
        int m = tid >> 1, hf = tid & 1;
#pragma unroll
        for (int j = 0; j < 4; j++) {
            float4 a = *(const float4*)&Qg[(size_t)(q0 + m) * HDIM + 32 * hf + 8 * j];
            float4 c = *(const float4*)&Qg[(size_t)(q0 + m) * HDIM + 32 * hf + 8 * j + 4];
            uint32_t w0h, w0l, w1h, w1l, w2h, w2l, w3h, w3l;
            h2split(a.x, a.y, w0h, w0l); h2split(a.z, a.w, w1h, w1l);
            h2split(c.x, c.y, w2h, w2l); h2split(c.z, c.w, w3h, w3l);
            *(uint4*)&Qh[m * AQ_W + 16 * hf + 4 * j] = make_uint4(w0h, w1h, w2h, w3h);
            *(uint4*)&Ql[m * AQ_W + 16 * hf + 4 * j] = make_uint4(w0l, w1l, w2l, w3l);
        }
    }

    float o[8][4];
#pragma unroll
    for (int jj = 0; jj < 8; jj++)
#pragma unroll
        for (int e = 0; e < 4; e++) o[jj][e] = 0.f;
    float m0r = -1e30f, m1r = -1e30f, l0 = 0.f, l1 = 0.f;

    for (int kt = 0; kt < SEQ; kt += 64) {
        __syncthreads();   // prev-tile reads done (and Q visible on iter 0)

        // ---- stage K tile: row r = tid/4, cols 16*(tid&3)..
        {
            int r = tid >> 2, q = tid & 3;
            const float* src = &Kg[(size_t)(kt + r) * HDIM + 16 * q];
            float4 a = *(const float4*)&src[0];
            float4 c = *(const float4*)&src[4];
            float4 d = *(const float4*)&src[8];
            float4 e = *(const float4*)&src[12];
            uint32_t wh[8], wl[8];
            h2split(a.x, a.y, wh[0], wl[0]); h2split(a.z, a.w, wh[1], wl[1]);
            h2split(c.x, c.y, wh[2], wl[2]); h2split(c.z, c.w, wh[3], wl[3]);
            h2split(d.x, d.y, wh[4], wl[4]); h2split(d.z, d.w, wh[5], wl[5]);
            h2split(e.x, e.y, wh[6], wl[6]); h2split(e.z, e.w, wh[7], wl[7]);
            *(uint4*)&Kh[r * AK_W + 8 * q]     = make_uint4(wh[0], wh[1], wh[2], wh[3]);
            *(uint4*)&Kh[r * AK_W + 8 * q + 4] = make_uint4(wh[4], wh[5], wh[6], wh[7]);
            *(uint4*)&Kl[r * AK_W + 8 * q]     = make_uint4(wl[0], wl[1], wl[2], wl[3]);
            *(uint4*)&Kl[r * AK_W + 8 * q + 4] = make_uint4(wl[4], wl[5], wl[6], wl[7]);
        }
        // ---- stage V tile pair-packed: pair p = tid/8, cols 8*(tid&7)..
        {
            int p = tid >> 3, q = tid & 7;
            const float* s0 = &Vg[(size_t)(kt + 2 * p) * HDIM + 8 * q];
            const float* s1 = &Vg[(size_t)(kt + 2 * p + 1) * HDIM + 8 * q];
            float4 a0 = *(const float4*)&s0[0], a1 = *(const float4*)&s0[4];
            float4 b0 = *(const float4*)&s1[0], b1 = *(const float4*)&s1[4];
            uint32_t wh[8], wl[8];
            h2split(a0.x, b0.x, wh[0], wl[0]); h2split(a0.y, b0.y, wh[1], wl[1]);
            h2split(a0.z, b0.z, wh[2], wl[2]); h2split(a0.w, b0.w, wh[3], wl[3]);
            h2split(a1.x, b1.x, wh[4], wl[4]); h2split(a1.y, b1.y, wh[5], wl[5]);
            h2split(a1.z, b1.z, wh[6], wl[6]); h2split(a1.w, b1.w, wh[7], wl[7]);
            *(uint4*)&Vh[p * AV_W + 8 * q]     = make_uint4(wh[0], wh[1], wh[2], wh[3]);
            *(uint4*)&Vh[p * AV_W + 8 * q + 4] = make_uint4(wh[4], wh[5], wh[6], wh[7]);
            *(uint4*)&Vl[p * AV_W + 8 * q]     = make_uint4(wl[0], wl[1], wl[2], wl[3]);
            *(uint4*)&Vl[p * AV_W + 8 * q + 4] = make_uint4(wl[4], wl[5], wl[6], wl[7]);
        }
        __syncthreads();

        // ---- S = Q @ K^T
        float s[8][4];
#pragma unroll
        for (int jj = 0; jj < 8; jj++)
#pragma unroll
            for (int e = 0; e < 4; e++) s[jj][e] = 0.f;

#pragma unroll
        for (int c = 0; c < 4; c++) {
            uint32_t fah[4], fal[4];
            fah[0] = Qh[qrow * AQ_W + 8 * c + t];
            fah[1] = Qh[(qrow + 8) * AQ_W + 8 * c + t];
            fah[2] = Qh[qrow * AQ_W + 8 * c + 4 + t];
            fah[3] = Qh[(qrow + 8) * AQ_W + 8 * c + 4 + t];
            fal[0] = Ql[qrow * AQ_W + 8 * c + t];
            fal[1] = Ql[(qrow + 8) * AQ_W + 8 * c + t];
            fal[2] = Ql[qrow * AQ_W + 8 * c + 4 + t];
            fal[3] = Ql[(qrow + 8) * AQ_W + 8 * c + 4 + t];
#pragma unroll
            for (int jj = 0; jj < 8; jj++) {
                int nn = jj * 8 + g;
                uint32_t bh[2], bl[2];
                bh[0] = Kh[nn * AK_W + 8 * c + t];
                bh[1] = Kh[nn * AK_W + 8 * c + 4 + t];
                bl[0] = Kl[nn * AK_W + 8 * c + t];
                bl[1] = Kl[nn * AK_W + 8 * c + 4 + t];
                mma16(s[jj], fah, bh);
                mma16(s[jj], fal, bh);
                mma16(s[jj], fah, bl);
            }
        }

        // ---- softmax update (mask loaded inline; additive)
        float vm0 = -1e30f, vm1 = -1e30f;
#pragma unroll
        for (int jj = 0; jj < 8; jj++) {
            int col = kt + jj * 8 + 2 * t;
            float2 mk0 = *(const float2*)&Mg[(size_t)(q0 + qrow) * SEQ + col];
            float2 mk1 = *(const float2*)&Mg[(size_t)(q0 + qrow + 8) * SEQ + col];
            s[jj][0] = s[jj][0] * 0.125f + mk0.x;
            s[jj][1] = s[jj][1] * 0.125f + mk0.y;
            s[jj][2] = s[jj][2] * 0.125f + mk1.x;
            s[jj][3] = s[jj][3] * 0.125f + mk1.y;
            vm0 = fmaxf(vm0, fmaxf(s[jj][0], s[jj][1]));
            vm1 = fmaxf(vm1, fmaxf(s[jj][2], s[jj][3]));
        }
        vm0 = fmaxf(vm0, __shfl_xor_sync(0xffffffffu, vm0, 1));
        vm0 = fmaxf(vm0, __shfl_xor_sync(0xffffffffu, vm0, 2));
        vm1 = fmaxf(vm1, __shfl_xor_sync(0xffffffffu, vm1, 1));
        vm1 = fmaxf(vm1, __shfl_xor_sync(0xffffffffu, vm1, 2));

        float mn0 = fmaxf(m0r, vm0), mn1 = fmaxf(m1r, vm1);
        float cor0 = __expf(m0r - mn0), cor1 = __expf(m1r - mn1);
        m0r = mn0; m1r = mn1;
        float rs0 = 0.f, rs1 = 0.f;
#pragma unroll
        for (int jj = 0; jj < 8; jj++) {
            s[jj][0] = __expf(s[jj][0] - mn0);
            s[jj][1] = __expf(s[jj][1] - mn0);
            s[jj][2] = __expf(s[jj][2] - mn1);
            s[jj][3] = __expf(s[jj][3] - mn1);
            rs0 += s[jj][0] + s[jj][1];
            rs1 += s[jj][2] + s[jj][3];
        }
        rs0 += __shfl_xor_sync(0xffffffffu, rs0, 1);
        rs0 += __shfl_xor_sync(0xffffffffu, rs0, 2);
        rs1 += __shfl_xor_sync(0xffffffffu, rs1, 1);
        rs1 += __shfl_xor_sync(0xffffffffu, rs1, 2);
        l0 = l0 * cor0 + rs0;
        l1 = l1 * cor1 + rs1;
#pragma unroll
        for (int jj = 0; jj < 8; jj++) {
            o[jj][0] *= cor0; o[jj][1] *= cor0;
            o[jj][2] *= cor1; o[jj][3] *= cor1;
        }

        // ---- O += P @ V : P fragments straight from s registers
#pragma unroll
        for (int c = 0; c < 4; c++) {
            uint32_t ph[4], pl[4];
            h2split(s[2 * c][0],     s[2 * c][1],     ph[0], pl[0]);
            h2split(s[2 * c][2],     s[2 * c][3],     ph[1], pl[1]);
            h2split(s[2 * c + 1][0], s[2 * c + 1][1], ph[2], pl[2]);
            h2split(s[2 * c + 1][2], s[2 * c + 1][3], ph[3], pl[3]);
#pragma unroll
            for (int jj = 0; jj < 8; jj++) {
                int nn = jj * 8 + g;
                uint32_t bh[2], bl[2];
                bh[0] = Vh[(8 * c + t) * AV_W + nn];
                bh[1] = Vh[(8 * c + 4 + t) * AV_W + nn];
                bl[0] = Vl[(8 * c + t) * AV_W + nn];
                bl[1] = Vl[(8 * c + 4 + t) * AV_W + nn];
                mma16(o[jj], ph, bh);
                mma16(o[jj], pl, bh);
                mma16(o[jj], ph, bl);
            }
        }
    }

    float inv0 = 1.f / l0, inv1 = 1.f / l1;
#pragma unroll
    for (int jj = 0; jj < 8; jj++) {
        size_t r0a = (size_t)(b * SEQ + q0 + qrow) * DMODEL + h * HDIM + jj * 8 + 2 * t;
        size_t r1a = (size_t)(b * SEQ + q0 + qrow + 8) * DMODEL + h * HDIM + jj * 8 + 2 * t;
        *(float2*)&g_vals[r0a] = make_float2(o[jj][0] * inv0, o[jj][1] * inv0);
        *(float2*)&g_vals[r1a] = make_float2(o[jj][2] * inv1, o[jj][3] * inv1);
    }
}

// ---------------------------------------------------------------------------
extern "C" void kernel_launch(void* const* d_in, const int* in_sizes, int n_in,
                              void* d_out, int out_size) {
    const float* x    = (const float*)d_in[0];
    const float* mask = (const float*)d_in[1];
    const float* Wqkv = (const float*)d_in[2];
    const float* bqkv = (const float*)d_in[3];
    const float* Wo   = (const float*)d_in[4];
    const float* bo   = (const float*)d_in[5];
    float* out = (float*)d_out;

    cudaFuncSetAttribute(qkv_kernel, cudaFuncAttributeMaxDynamicSharedMemorySize,
                         GEMM_BYTES);
    cudaFuncSetAttribute(proj_kernel, cudaFuncAttributeMaxDynamicSharedMemorySize,
                         GEMM_BYTES);
    cudaFuncSetAttribute(attn_kernel, cudaFuncAttributeMaxDynamicSharedMemorySize,
                         ATTN_BYTES);

    dim3 gq(D3 / 128, (BATCH * SEQ) / 128);
    qkv_kernel<<<gq, 256, GEMM_BYTES>>>(x, Wqkv, bqkv);

    dim3 ga(SEQ / 128, NHEAD, BATCH);
    attn_kernel<<<ga, 256, ATTN_BYTES>>>(mask);

    dim3 gp(DMODEL / 128, (BATCH * SEQ) / 128);
    proj_kernel<<<gp, 256, GEMM_BYTES>>>(Wo, bo, out);
}